// round 15
// baseline (speedup 1.0000x reference)
#include <cuda_runtime.h>
#include <cuda_pipeline.h>
#include <math.h>

// Problem constants (fixed by setup_inputs)
#define B       32
#define HQ      32
#define HKV     8
#define G       4      // HQ / HKV
#define D       128
#define BS      16     // block_size
#define MAXB    256    // max_blocks
#define CHUNK   128    // tokens per split
#define NS      32     // max splits = 4096 / CHUNK
#define NWARP   4
#define NTHR    (NWARP * 32)
#define ROWF    132    // padded K-row stride in floats (528B) -> conflict-free LDS

#define QSCALE  (0.08838834764831845f * 1.4426950408889634f)  // SCALE * log2(e)
#define NEG_BIG (-1e30f)
#define FULLM   0xffffffffu

// Scratch: partial (unnormalized) outputs + packed (m, l) per (b, hkv, split, g)
__device__ float  g_part_acc[B * HKV * NS * G * D];
__device__ float2 g_part_ml [B * HKV * NS * G];

__device__ __forceinline__ float warp_allmax(float v) {
    v = fmaxf(v, __shfl_xor_sync(FULLM, v, 16));
    v = fmaxf(v, __shfl_xor_sync(FULLM, v, 8));
    v = fmaxf(v, __shfl_xor_sync(FULLM, v, 4));
    v = fmaxf(v, __shfl_xor_sync(FULLM, v, 2));
    v = fmaxf(v, __shfl_xor_sync(FULLM, v, 1));
    return v;
}
__device__ __forceinline__ float warp_allsum(float v) {
    v += __shfl_xor_sync(FULLM, v, 16);
    v += __shfl_xor_sync(FULLM, v, 8);
    v += __shfl_xor_sync(FULLM, v, 4);
    v += __shfl_xor_sync(FULLM, v, 2);
    v += __shfl_xor_sync(FULLM, v, 1);
    return v;
}
__device__ __forceinline__ void prefetch_l2(const void* p) {
    asm volatile("prefetch.global.L2 [%0];" :: "l"(p));
}

__global__ __launch_bounds__(NTHR)
void attn_split_kernel(const float* __restrict__ q,
                       const float* __restrict__ kc,
                       const float* __restrict__ vc,
                       const int*   __restrict__ seqlens,
                       const int*   __restrict__ btab)
{
    extern __shared__ float smem[];
    float* qs   = smem;                         // G*D = 512 floats (pre-scaled q)
    float* Ks   = qs + G * D;                   // CHUNK * ROWF = 16896 floats
    float* ps   = Ks + CHUNK * ROWF;            // NWARP*32*4 = 512 floats
    float* smm  = ps + NWARP * 32 * 4;          // NWARP*G
    float* sml  = smm + NWARP * G;              // NWARP*G
    float* sma  = Ks;                           // ALIAS: K tile dead after scores

    const int b  = blockIdx.x;
    const int h  = blockIdx.y;
    const int sp = blockIdx.z;

    const int L     = seqlens[b];
    const int start = sp * CHUNK;
    if (start >= L) return;
    const int end = min(start + CHUNK, L);

    const int tid  = threadIdx.x;
    const int lane = tid & 31;
    const int w    = tid >> 5;

    // Blocks touched by this warp's 32 tokens (start, w*32 both 16-aligned)
    const int* bt   = btab + b * MAXB;
    const int  blkA = bt[(start >> 4) + w * 2];
    const int  blkB = bt[(start >> 4) + w * 2 + 1];

    // --- stage K tile: warp w stages rows [w*32, w*32+32); lane = 16B chunk ---
    {
        const float* kb0 = kc + ((blkA * BS) * HKV + h) * D + lane * 4;
        const float* kb1 = kc + ((blkB * BS) * HKV + h) * D + lane * 4;
        float* d0 = Ks + (w * 32) * ROWF + lane * 4;
#pragma unroll
        for (int r = 0; r < 16; r++)
            __pipeline_memcpy_async(d0 + r * ROWF, kb0 + r * (HKV * D), 16);
        float* d1 = Ks + (w * 32 + 16) * ROWF + lane * 4;
#pragma unroll
        for (int r = 0; r < 16; r++)
            __pipeline_memcpy_async(d1 + r * ROWF, kb1 + r * (HKV * D), 16);
        __pipeline_commit();
    }

    // --- prefetch this warp's V rows to L2 (consumed in PV phase later) ---
    {
        const float* vp0 = vc + ((blkA * BS) * HKV + h) * D;
        const float* vp1 = vc + ((blkB * BS) * HKV + h) * D;
        const int r4 = lane >> 3;          // 0..3
        const int c  = lane & 7;           // line within the 512B row
#pragma unroll
        for (int rr = 0; rr < 4; rr++) {
            const int row = rr * 4 + r4;   // 0..15
            prefetch_l2(vp0 + row * (HKV * D) + (c & 3) * 32 + (c >> 2) * 64);
            prefetch_l2(vp1 + row * (HKV * D) + (c & 3) * 32 + (c >> 2) * 64);
        }
    }

    // --- stage q (pre-scaled), 128 float4 by 128 threads ---
    {
        const float4* qg = (const float4*)(q + (b * HQ + h * G) * D);
        float4* qd = (float4*)qs;
#pragma unroll
        for (int i = tid; i < G * D / 4; i += NTHR) {
            float4 v = qg[i];
            v.x *= QSCALE; v.y *= QSCALE; v.z *= QSCALE; v.w *= QSCALE;
            qd[i] = v;
        }
    }
    __syncthreads();                 // q visible to all
    __pipeline_wait_prior(0);        // own warp's K rows landed
    __syncwarp();

    float M0 = NEG_BIG, M1 = NEG_BIG, M2 = NEG_BIG, M3 = NEG_BIG;
    float l0 = 0.f, l1 = 0.f, l2 = 0.f, l3 = 0.f;
    float4 a0 = {0,0,0,0}, a1 = {0,0,0,0}, a2 = {0,0,0,0}, a3 = {0,0,0,0};

    const bool wvalid = (start + w * 32) < end;
    if (wvalid) {
        const int  myrow = w * 32 + lane;
        const bool valid = (start + myrow) < end;

        // --- scores: lane = token, dot over D from smem (q loads broadcast) ---
        float s0 = 0.f, s1 = 0.f, s2 = 0.f, s3 = 0.f;
        const float4* krow = (const float4*)(Ks + myrow * ROWF);
        const float4* q4p  = (const float4*)qs;
#pragma unroll
        for (int c = 0; c < 32; c++) {
            const float4 k4 = krow[c];
            const float4 qa = q4p[c];
            const float4 qb = q4p[32 + c];
            const float4 qcc = q4p[64 + c];
            const float4 qd = q4p[96 + c];
            s0 += qa.x*k4.x + qa.y*k4.y + qa.z*k4.z + qa.w*k4.w;
            s1 += qb.x*k4.x + qb.y*k4.y + qb.z*k4.z + qb.w*k4.w;
            s2 += qcc.x*k4.x + qcc.y*k4.y + qcc.z*k4.z + qcc.w*k4.w;
            s3 += qd.x*k4.x + qd.y*k4.y + qd.z*k4.z + qd.w*k4.w;
        }
        if (!valid) { s0 = s1 = s2 = s3 = NEG_BIG; }

        // one max + one sum reduce per tile (not per token)
        M0 = warp_allmax(s0); M1 = warp_allmax(s1);
        M2 = warp_allmax(s2); M3 = warp_allmax(s3);

        const float p0 = exp2f(s0 - M0);   // invalid lanes -> exp2(-huge) = 0
        const float p1 = exp2f(s1 - M1);
        const float p2 = exp2f(s2 - M2);
        const float p3 = exp2f(s3 - M3);

        l0 = warp_allsum(p0); l1 = warp_allsum(p1);
        l2 = warp_allsum(p2); l3 = warp_allsum(p3);

        ((float4*)ps)[w * 32 + lane] = make_float4(p0, p1, p2, p3);
        __syncwarp();

        // --- PV: lanes own dims; V from GMEM (L2-warm), batched by 4 ---
        const float* vb0 = vc + ((blkA * BS) * HKV + h) * D + lane * 4;
        const float* vb1 = vc + ((blkB * BS) * HKV + h) * D + lane * 4;
        const float4* pw = (const float4*)ps + w * 32;
#pragma unroll
        for (int t0 = 0; t0 < 32; t0 += 4) {
            float4 v[4];
#pragma unroll
            for (int j = 0; j < 4; j++) {
                const int tt = t0 + j;
                const float* vb = (tt < 16) ? (vb0 + tt * (HKV * D))
                                            : (vb1 + (tt - 16) * (HKV * D));
                v[j] = *(const float4*)vb;
            }
#pragma unroll
            for (int j = 0; j < 4; j++) {
                const float4 pp = pw[t0 + j];
                a0.x += pp.x*v[j].x; a0.y += pp.x*v[j].y; a0.z += pp.x*v[j].z; a0.w += pp.x*v[j].w;
                a1.x += pp.y*v[j].x; a1.y += pp.y*v[j].y; a1.z += pp.y*v[j].z; a1.w += pp.y*v[j].w;
                a2.x += pp.z*v[j].x; a2.y += pp.z*v[j].y; a2.z += pp.z*v[j].z; a2.w += pp.z*v[j].w;
                a3.x += pp.w*v[j].x; a3.y += pp.w*v[j].y; a3.z += pp.w*v[j].z; a3.w += pp.w*v[j].w;
            }
        }
    }

    // --- all warps done reading Ks before writing the aliased merge buffer ---
    __syncthreads();

    if (lane == 0) {
        smm[w * G + 0] = M0; smm[w * G + 1] = M1; smm[w * G + 2] = M2; smm[w * G + 3] = M3;
        sml[w * G + 0] = l0; sml[w * G + 1] = l1; sml[w * G + 2] = l2; sml[w * G + 3] = l3;
    }
    ((float4*)(sma + (w * G + 0) * D))[lane] = a0;
    ((float4*)(sma + (w * G + 1) * D))[lane] = a1;
    ((float4*)(sma + (w * G + 2) * D))[lane] = a2;
    ((float4*)(sma + (w * G + 3) * D))[lane] = a3;
    __syncthreads();

    // --- merge 4 warps: warp w handles head w ---
    {
        const int gg = w;
        float Mm = NEG_BIG;
#pragma unroll
        for (int ww = 0; ww < NWARP; ww++)
            Mm = fmaxf(Mm, smm[ww * G + gg]);

        float Ls = 0.f;
        float4 o = {0,0,0,0};
#pragma unroll
        for (int ww = 0; ww < NWARP; ww++) {
            const float e = exp2f(smm[ww * G + gg] - Mm);
            Ls += e * sml[ww * G + gg];
            const float4 x = ((const float4*)(sma + (ww * G + gg) * D))[lane];
            o.x += e * x.x; o.y += e * x.y; o.z += e * x.z; o.w += e * x.w;
        }

        const int idx = ((b * HKV + h) * NS + sp) * G + gg;
        if (lane == 0)
            g_part_ml[idx] = make_float2(Mm, Ls);
        ((float4*)(g_part_acc + idx * D))[lane] = o;
    }
}

// Combine: 1024 CTAs x 256 threads = 2 split-lanes x 128 dims.
// Each lane owns splits s + 2k (<= 16): up to two 8-deep predicated batches
// with early break (avg nsp = 16 -> 1 batch). MLP = 16 per batch.
__global__ __launch_bounds__(256)
void attn_combine_kernel(const int* __restrict__ seqlens,
                         float* __restrict__ out)
{
    __shared__ float sO[2][D];
    __shared__ float sL[2];

    const int bh = blockIdx.x;          // b * HQ + hq
    const int b  = bh / HQ;
    const int hq = bh % HQ;
    const int h  = hq / G;
    const int g  = hq % G;
    const int d  = threadIdx.x & (D - 1);
    const int s  = threadIdx.x >> 7;    // split lane 0..1

    const int L   = seqlens[b];
    const int nsp = min(NS, (L + CHUNK - 1) / CHUNK);

    const int base = ((b * HKV + h) * NS) * G + g;  // + sp*G per split

    const float mref = g_part_ml[base].x;   // split 0 always valid (broadcast)

    float Ls = 0.f, o = 0.f;
#pragma unroll
    for (int batch = 0; batch < 2; batch++) {
        float2 ml[8];
        float  av[8];
#pragma unroll
        for (int k = 0; k < 8; k++) {
            const int spi = s + 2 * (batch * 8 + k);
            const bool vld = (spi < nsp);
            const int i0 = base + spi * G;
            ml[k] = vld ? g_part_ml[i0]          : make_float2(NEG_BIG, 0.f);
            av[k] = vld ? g_part_acc[i0 * D + d] : 0.f;
        }
#pragma unroll
        for (int k = 0; k < 8; k++) {
            const float e = exp2f(ml[k].x - mref);   // NEG_BIG -> 0
            Ls += e * ml[k].y;
            o  += e * av[k];
        }
        if (nsp <= 16) break;   // second batch all empty for short sequences
    }

    sO[s][d] = o;
    if (d == 0) sL[s] = Ls;
    __syncthreads();

    if (s == 0) {
        const float oT = sO[0][d] + sO[1][d];
        const float LT = sL[0] + sL[1];
        out[bh * D + d] = oT / LT;
    }
}

extern "C" void kernel_launch(void* const* d_in, const int* in_sizes, int n_in,
                              void* d_out, int out_size)
{
    const float* q   = (const float*)d_in[0];
    const float* kc  = (const float*)d_in[1];
    const float* vc  = (const float*)d_in[2];
    const int*   sl  = (const int*)  d_in[3];
    const int*   bt  = (const int*)  d_in[4];
    float*       out = (float*)d_out;

    // qs + Ks + ps + smm + sml (sma aliases Ks)
    const int smem_bytes = (G * D + CHUNK * ROWF + NWARP * 32 * 4 +
                            NWARP * G * 2) * sizeof(float);

    // > 48KB dynamic smem requires opt-in (idempotent; not a stream op)
    cudaFuncSetAttribute(attn_split_kernel,
                         cudaFuncAttributeMaxDynamicSharedMemorySize, smem_bytes);

    dim3 grid1(B, HKV, NS);
    attn_split_kernel<<<grid1, NTHR, smem_bytes>>>(q, kc, vc, sl, bt);
    attn_combine_kernel<<<B * HQ, 256>>>(sl, out);
}

// round 16
// speedup vs baseline: 1.6291x; 1.6291x over previous
#include <cuda_runtime.h>
#include <cuda_pipeline.h>
#include <math.h>

// Problem constants (fixed by setup_inputs)
#define B       32
#define HQ      32
#define HKV     8
#define G       4      // HQ / HKV
#define D       128
#define BS      16     // block_size
#define MAXB    256    // max_blocks
#define CHUNK   64     // tokens per split
#define NS      64     // max splits = 4096 / CHUNK
#define NWARP   2
#define NTHR    (NWARP * 32)
#define ROWF    132    // padded K-row stride in floats (528B) -> conflict-free LDS

#define QSCALE  (0.08838834764831845f * 1.4426950408889634f)  // SCALE * log2(e)
#define NEG_BIG (-1e30f)
#define FULLM   0xffffffffu

// Scratch: partial (unnormalized) outputs + packed (m, l) per (b, hkv, split, g)
__device__ float  g_part_acc[B * HKV * NS * G * D];
__device__ float2 g_part_ml [B * HKV * NS * G];

__device__ __forceinline__ float warp_allmax(float v) {
    v = fmaxf(v, __shfl_xor_sync(FULLM, v, 16));
    v = fmaxf(v, __shfl_xor_sync(FULLM, v, 8));
    v = fmaxf(v, __shfl_xor_sync(FULLM, v, 4));
    v = fmaxf(v, __shfl_xor_sync(FULLM, v, 2));
    v = fmaxf(v, __shfl_xor_sync(FULLM, v, 1));
    return v;
}
__device__ __forceinline__ float warp_allsum(float v) {
    v += __shfl_xor_sync(FULLM, v, 16);
    v += __shfl_xor_sync(FULLM, v, 8);
    v += __shfl_xor_sync(FULLM, v, 4);
    v += __shfl_xor_sync(FULLM, v, 2);
    v += __shfl_xor_sync(FULLM, v, 1);
    return v;
}
__device__ __forceinline__ void prefetch_l2(const void* p) {
    asm volatile("prefetch.global.L2 [%0];" :: "l"(p));
}

__global__ __launch_bounds__(NTHR)
void attn_split_kernel(const float* __restrict__ q,
                       const float* __restrict__ kc,
                       const float* __restrict__ vc,
                       const int*   __restrict__ seqlens,
                       const int*   __restrict__ btab)
{
    extern __shared__ float smem[];
    float* qs   = smem;                         // G*D = 512 floats (pre-scaled q)
    float* Ks   = qs + G * D;                   // CHUNK * ROWF = 8448 floats
    float* ps   = Ks + CHUNK * ROWF;            // NWARP*32*4 = 256 floats
    float* smm  = ps + NWARP * 32 * 4;          // NWARP*G
    float* sml  = smm + NWARP * G;              // NWARP*G
    float* sma  = Ks;                           // ALIAS: K tile dead after scores

    const int b  = blockIdx.x;
    const int h  = blockIdx.y;
    const int sp = blockIdx.z;

    const int L     = seqlens[b];
    const int start = sp * CHUNK;
    if (start >= L) return;
    const int end = min(start + CHUNK, L);

    const int tid  = threadIdx.x;
    const int lane = tid & 31;
    const int w    = tid >> 5;

    // Blocks touched by this warp's 32 tokens (start, w*32 both 16-aligned)
    const int* bt   = btab + b * MAXB;
    const int  blkA = bt[(start >> 4) + w * 2];
    const int  blkB = bt[(start >> 4) + w * 2 + 1];

    // --- stage K tile: warp w stages rows [w*32, w*32+32); lane = 16B chunk ---
    {
        const float* kb0 = kc + ((blkA * BS) * HKV + h) * D + lane * 4;
        const float* kb1 = kc + ((blkB * BS) * HKV + h) * D + lane * 4;
        float* d0 = Ks + (w * 32) * ROWF + lane * 4;
#pragma unroll
        for (int r = 0; r < 16; r++)
            __pipeline_memcpy_async(d0 + r * ROWF, kb0 + r * (HKV * D), 16);
        float* d1 = Ks + (w * 32 + 16) * ROWF + lane * 4;
#pragma unroll
        for (int r = 0; r < 16; r++)
            __pipeline_memcpy_async(d1 + r * ROWF, kb1 + r * (HKV * D), 16);
        __pipeline_commit();
    }

    // --- prefetch this warp's V rows to L2 (addresses known now; consumed in
    //     the PV phase ~2us later). 32 rows x 512B = 128 lines / 32 lanes.
    {
        const float* vp0 = vc + ((blkA * BS) * HKV + h) * D;
        const float* vp1 = vc + ((blkB * BS) * HKV + h) * D;
        const int r4 = lane >> 3;          // 0..3: which row quartet per round
        const int c  = lane & 7;           // 0..7 -> line within the 512B row
#pragma unroll
        for (int rr = 0; rr < 4; rr++) {
            const int row = rr * 4 + r4;   // 0..15
            prefetch_l2(vp0 + row * (HKV * D) + (c & 3) * 32 + (c >> 2) * 64);
            prefetch_l2(vp1 + row * (HKV * D) + (c & 3) * 32 + (c >> 2) * 64);
        }
    }

    // --- stage q (pre-scaled), 128 float4 by 64 threads ---
    {
        const float4* qg = (const float4*)(q + (b * HQ + h * G) * D);
        float4* qd = (float4*)qs;
#pragma unroll
        for (int i = tid; i < G * D / 4; i += NTHR) {
            float4 v = qg[i];
            v.x *= QSCALE; v.y *= QSCALE; v.z *= QSCALE; v.w *= QSCALE;
            qd[i] = v;
        }
    }
    __syncthreads();                 // q visible to all
    __pipeline_wait_prior(0);        // own warp's K rows landed
    __syncwarp();

    float M0 = NEG_BIG, M1 = NEG_BIG, M2 = NEG_BIG, M3 = NEG_BIG;
    float l0 = 0.f, l1 = 0.f, l2 = 0.f, l3 = 0.f;
    float4 a0 = {0,0,0,0}, a1 = {0,0,0,0}, a2 = {0,0,0,0}, a3 = {0,0,0,0};

    const bool wvalid = (start + w * 32) < end;
    if (wvalid) {
        const int  myrow = w * 32 + lane;
        const bool valid = (start + myrow) < end;

        // --- scores: lane = token, dot over D from smem (q loads broadcast) ---
        float s0 = 0.f, s1 = 0.f, s2 = 0.f, s3 = 0.f;
        const float4* krow = (const float4*)(Ks + myrow * ROWF);
        const float4* q4p  = (const float4*)qs;
#pragma unroll
        for (int c = 0; c < 32; c++) {
            const float4 k4 = krow[c];
            const float4 qa = q4p[c];
            const float4 qb = q4p[32 + c];
            const float4 qcc = q4p[64 + c];
            const float4 qd = q4p[96 + c];
            s0 += qa.x*k4.x + qa.y*k4.y + qa.z*k4.z + qa.w*k4.w;
            s1 += qb.x*k4.x + qb.y*k4.y + qb.z*k4.z + qb.w*k4.w;
            s2 += qcc.x*k4.x + qcc.y*k4.y + qcc.z*k4.z + qcc.w*k4.w;
            s3 += qd.x*k4.x + qd.y*k4.y + qd.z*k4.z + qd.w*k4.w;
        }
        if (!valid) { s0 = s1 = s2 = s3 = NEG_BIG; }

        // one max + one sum reduce per tile (not per token)
        M0 = warp_allmax(s0); M1 = warp_allmax(s1);
        M2 = warp_allmax(s2); M3 = warp_allmax(s3);

        const float p0 = exp2f(s0 - M0);   // invalid lanes -> exp2(-huge) = 0
        const float p1 = exp2f(s1 - M1);
        const float p2 = exp2f(s2 - M2);
        const float p3 = exp2f(s3 - M3);

        l0 = warp_allsum(p0); l1 = warp_allsum(p1);
        l2 = warp_allsum(p2); l3 = warp_allsum(p3);

        ((float4*)ps)[w * 32 + lane] = make_float4(p0, p1, p2, p3);
        __syncwarp();

        // --- PV: lanes own dims; V from GMEM (L2-warm), batched by 4 ---
        const float* vb0 = vc + ((blkA * BS) * HKV + h) * D + lane * 4;
        const float* vb1 = vc + ((blkB * BS) * HKV + h) * D + lane * 4;
        const float4* pw = (const float4*)ps + w * 32;
#pragma unroll
        for (int t0 = 0; t0 < 32; t0 += 4) {
            float4 v[4];
#pragma unroll
            for (int j = 0; j < 4; j++) {
                const int tt = t0 + j;
                const float* vb = (tt < 16) ? (vb0 + tt * (HKV * D))
                                            : (vb1 + (tt - 16) * (HKV * D));
                v[j] = *(const float4*)vb;
            }
#pragma unroll
            for (int j = 0; j < 4; j++) {
                const float4 pp = pw[t0 + j];
                a0.x += pp.x*v[j].x; a0.y += pp.x*v[j].y; a0.z += pp.x*v[j].z; a0.w += pp.x*v[j].w;
                a1.x += pp.y*v[j].x; a1.y += pp.y*v[j].y; a1.z += pp.y*v[j].z; a1.w += pp.y*v[j].w;
                a2.x += pp.z*v[j].x; a2.y += pp.z*v[j].y; a2.z += pp.z*v[j].z; a2.w += pp.z*v[j].w;
                a3.x += pp.w*v[j].x; a3.y += pp.w*v[j].y; a3.z += pp.w*v[j].z; a3.w += pp.w*v[j].w;
            }
        }
    }

    // --- all warps done reading Ks before writing the aliased merge buffer ---
    __syncthreads();

    if (lane == 0) {
        smm[w * G + 0] = M0; smm[w * G + 1] = M1; smm[w * G + 2] = M2; smm[w * G + 3] = M3;
        sml[w * G + 0] = l0; sml[w * G + 1] = l1; sml[w * G + 2] = l2; sml[w * G + 3] = l3;
    }
    ((float4*)(sma + (w * G + 0) * D))[lane] = a0;
    ((float4*)(sma + (w * G + 1) * D))[lane] = a1;
    ((float4*)(sma + (w * G + 2) * D))[lane] = a2;
    ((float4*)(sma + (w * G + 3) * D))[lane] = a3;
    __syncthreads();

    // --- merge 2 warps: warp w handles heads {2w, 2w+1} ---
#pragma unroll
    for (int k = 0; k < 2; k++) {
        const int gg = 2 * w + k;
        const float Ma = smm[0 * G + gg];
        const float Mb = smm[1 * G + gg];
        const float M  = fmaxf(Ma, Mb);
        const float e0 = exp2f(Ma - M);
        const float e1 = exp2f(Mb - M);
        const float Ls = e0 * sml[0 * G + gg] + e1 * sml[1 * G + gg];

        const float4 x0 = ((const float4*)(sma + (0 * G + gg) * D))[lane];
        const float4 x1 = ((const float4*)(sma + (1 * G + gg) * D))[lane];
        float4 o;
        o.x = e0 * x0.x + e1 * x1.x;
        o.y = e0 * x0.y + e1 * x1.y;
        o.z = e0 * x0.z + e1 * x1.z;
        o.w = e0 * x0.w + e1 * x1.w;

        const int idx = ((b * HKV + h) * NS + sp) * G + gg;
        if (lane == 0)
            g_part_ml[idx] = make_float2(M, Ls);
        ((float4*)(g_part_acc + idx * D))[lane] = o;
    }
}

// Combine: 1024 CTAs x 256 threads = 2 split-lanes x 128 dims.
// ~6 CTAs/SM -> ~1.15 waves. Each lane owns splits s + 2k (<= 32), consumed
// in up to four 8-deep predicated batches with early break (MLP = 16).
__global__ __launch_bounds__(256)
void attn_combine_kernel(const int* __restrict__ seqlens,
                         float* __restrict__ out)
{
    __shared__ float sO[2][D];
    __shared__ float sL[2];

    const int bh = blockIdx.x;          // b * HQ + hq
    const int b  = bh / HQ;
    const int hq = bh % HQ;
    const int h  = hq / G;
    const int g  = hq % G;
    const int d  = threadIdx.x & (D - 1);
    const int s  = threadIdx.x >> 7;    // split lane 0..1

    const int L   = seqlens[b];
    const int nsp = min(NS, (L + CHUNK - 1) / CHUNK);

    const int base = ((b * HKV + h) * NS) * G + g;  // + sp*G per split

    const float mref = g_part_ml[base].x;   // split 0 always valid (broadcast)

    float Ls = 0.f, o = 0.f;
#pragma unroll
    for (int batch = 0; batch < 4; batch++) {
        float2 ml[8];
        float  av[8];
#pragma unroll
        for (int k = 0; k < 8; k++) {
            const int spi = s + 2 * (batch * 8 + k);
            const bool vld = (spi < nsp);
            const int i0 = base + spi * G;
            ml[k] = vld ? g_part_ml[i0]          : make_float2(NEG_BIG, 0.f);
            av[k] = vld ? g_part_acc[i0 * D + d] : 0.f;
        }
#pragma unroll
        for (int k = 0; k < 8; k++) {
            const float e = exp2f(ml[k].x - mref);   // NEG_BIG -> 0
            Ls += e * ml[k].y;
            o  += e * av[k];
        }
        if (nsp <= 16 * (batch + 1)) break;   // remaining batches all empty
    }

    sO[s][d] = o;
    if (d == 0) sL[s] = Ls;
    __syncthreads();

    if (s == 0) {
        const float oT = sO[0][d] + sO[1][d];
        const float LT = sL[0] + sL[1];
        out[bh * D + d] = oT / LT;
    }
}

extern "C" void kernel_launch(void* const* d_in, const int* in_sizes, int n_in,
                              void* d_out, int out_size)
{
    const float* q   = (const float*)d_in[0];
    const float* kc  = (const float*)d_in[1];
    const float* vc  = (const float*)d_in[2];
    const int*   sl  = (const int*)  d_in[3];
    const int*   bt  = (const int*)  d_in[4];
    float*       out = (float*)d_out;

    // qs + Ks + ps + smm + sml (sma aliases Ks)
    const int smem_bytes = (G * D + CHUNK * ROWF + NWARP * 32 * 4 +
                            NWARP * G * 2) * sizeof(float);

    dim3 grid1(B, HKV, NS);
    attn_split_kernel<<<grid1, NTHR, smem_bytes>>>(q, kc, vc, sl, bt);
    attn_combine_kernel<<<B * HQ, 256>>>(sl, out);
}